// round 6
// baseline (speedup 1.0000x reference)
#include <cuda_runtime.h>
#include <cuda_fp16.h>
#include <cstdint>

#define NMAX 100000
#define EMAX 1600000
#define DIM 64
#define PACKMAX (EMAX + 3 * NMAX + 64)

// ---- scratch (__device__ globals; alloc-free rule) -------------------------
__device__ int    g_cnt[NMAX];          // per-node degree
__device__ int    g_off[NMAX];          // bin offsets (padded)
__device__ int    g_cur[NMAX];          // write cursors
__device__ int    g_cursor;             // global bin allocator
__device__ float4 g_pack[PACKMAX];      // binned records: (src, er, ei, 0)
__device__ uint4  g_h[NMAX * 16];       // fp16 interleaved h: per (node,l16):
                                        //   4 half hr | 4 half hi  (16 B)
__device__ float  g_zr[NMAX * DIM];
__device__ float  g_zi[NMAX * DIM];

static __device__ __forceinline__ int round4(int x) { return (x + 3) & ~3; }

static __device__ __forceinline__ unsigned long long pk2(float a, float b) {
    unsigned long long r;
    asm("mov.b64 %0, {%1, %2};" : "=l"(r) : "f"(a), "f"(b));
    return r;
}
static __device__ __forceinline__ void unpk2(unsigned long long v,
                                             float& a, float& b) {
    asm("mov.b64 {%0, %1}, %2;" : "=f"(a), "=f"(b) : "l"(v));
}
static __device__ __forceinline__ unsigned long long fma2(
        unsigned long long a, unsigned long long b, unsigned long long c) {
    unsigned long long d;
    asm("fma.rn.f32x2 %0, %1, %2, %3;" : "=l"(d) : "l"(a), "l"(b), "l"(c));
    return d;
}

// ---------------------------------------------------------------------------
// K0: zero cnt + cursor, convert h to interleaved fp16 (n*16 threads)
// ---------------------------------------------------------------------------
__global__ void init_kernel(const float* __restrict__ hr,
                            const float* __restrict__ hi, int n) {
    int t = blockIdx.x * blockDim.x + threadIdx.x;
    if (t == 0) g_cursor = 0;
    if (t < n) g_cnt[t] = 0;
    if (t < n * 16) {
        float4 r = __ldg(reinterpret_cast<const float4*>(hr) + t);
        float4 i = __ldg(reinterpret_cast<const float4*>(hi) + t);
        __half2 a = __floats2half2_rn(r.x, r.y);
        __half2 b = __floats2half2_rn(r.z, r.w);
        __half2 c = __floats2half2_rn(i.x, i.y);
        __half2 d = __floats2half2_rn(i.z, i.w);
        uint4 o;
        o.x = *reinterpret_cast<unsigned*>(&a);
        o.y = *reinterpret_cast<unsigned*>(&b);
        o.z = *reinterpret_cast<unsigned*>(&c);
        o.w = *reinterpret_cast<unsigned*>(&d);
        g_h[t] = o;
    }
}

// ---------------------------------------------------------------------------
// K1: histogram of dst
// ---------------------------------------------------------------------------
__global__ void hist_kernel(const int* __restrict__ dst, int E) {
    int e = blockIdx.x * blockDim.x + threadIdx.x;
    if (e < E) atomicAdd(&g_cnt[dst[e]], 1);
}

// ---------------------------------------------------------------------------
// K2: assign bin offsets (order-free: warp scan + one atomic per warp),
//     zero-fill padding slots.
// ---------------------------------------------------------------------------
__global__ void offsets_kernel(int n) {
    int i = blockIdx.x * blockDim.x + threadIdx.x;
    int lane = threadIdx.x & 31;
    int deg = (i < n) ? g_cnt[i] : 0;
    int v = round4(deg);
    int x = v;
    #pragma unroll
    for (int o = 1; o < 32; o <<= 1) {
        int y = __shfl_up_sync(0xffffffffu, x, o);
        if (lane >= o) x += y;
    }
    int base = 0;
    if (lane == 31) base = atomicAdd(&g_cursor, x);
    base = __shfl_sync(0xffffffffu, base, 31);
    int off = base + x - v;
    if (i < n) {
        g_off[i] = off;
        g_cur[i] = off;
        for (int t = deg; t < v; t++)
            g_pack[off + t] = make_float4(0.f, 0.f, 0.f, 0.f);
    }
}

// ---------------------------------------------------------------------------
// K3: scatter packed records into dst bins.  Coefficient excludes d[dst].
// ---------------------------------------------------------------------------
__global__ void permute_kernel(const float* __restrict__ d,
                               const float* __restrict__ wr,
                               const float* __restrict__ wi,
                               const int*   __restrict__ src,
                               const int*   __restrict__ dst,
                               int E) {
    int e = blockIdx.x * blockDim.x + threadIdx.x;
    if (e >= E) return;
    int s  = src[e];
    int dd = dst[e];
    float ds = __ldg(&d[s]);
    int slot = atomicAdd(&g_cur[dd], 1);
    g_pack[slot] = make_float4(__int_as_float(s), ds * wr[e], ds * wi[e], 0.f);
}

// ---------------------------------------------------------------------------
// K4: edge gather-reduce.  16 threads/node, batch-prefetch 16 records
// coalesced, shuffle-broadcast; ONE 16B fp16 gather per edge per lane.
// ---------------------------------------------------------------------------
__global__ __launch_bounds__(256)
void edge_kernel(const float* __restrict__ d, int n) {
    int node = blockIdx.x * 16 + (threadIdx.x >> 4);
    int l16  = threadIdx.x & 15;
    unsigned hmask = (threadIdx.x & 16) ? 0xFFFF0000u : 0x0000FFFFu;

    int deg4 = 0, start = 0;
    if (node < n) {
        start = g_off[node];
        deg4  = round4(g_cnt[node]);
    }
    const float4* packp = g_pack + start;

    float4 ar = make_float4(0.f, 0.f, 0.f, 0.f);
    float4 ai = make_float4(0.f, 0.f, 0.f, 0.f);

    for (int base = 0; base < deg4; base += 16) {
        int m = min(16, deg4 - base);   // multiple of 4
        float4 p = make_float4(0.f, 0.f, 0.f, 0.f);
        if (l16 < m) p = __ldg(&packp[base + l16]);
        int ps = __float_as_int(p.x);

        #pragma unroll
        for (int c = 0; c < 4; c++) {
            if (c * 4 < m) {
                #pragma unroll
                for (int qq = 0; qq < 4; qq++) {
                    int q = c * 4 + qq;
                    int   s  = __shfl_sync(hmask, ps,  q, 16);
                    float er = __shfl_sync(hmask, p.y, q, 16);
                    float ei = __shfl_sync(hmask, p.z, q, 16);
                    uint4 hv = __ldg(&g_h[(s << 4) + l16]);
                    float2 r01 = __half22float2(*reinterpret_cast<__half2*>(&hv.x));
                    float2 r23 = __half22float2(*reinterpret_cast<__half2*>(&hv.y));
                    float2 i01 = __half22float2(*reinterpret_cast<__half2*>(&hv.z));
                    float2 i23 = __half22float2(*reinterpret_cast<__half2*>(&hv.w));
                    ar.x += er * r01.x - ei * i01.x;
                    ar.y += er * r01.y - ei * i01.y;
                    ar.z += er * r23.x - ei * i23.x;
                    ar.w += er * r23.y - ei * i23.y;
                    ai.x += ei * r01.x + er * i01.x;
                    ai.y += ei * r01.y + er * i01.y;
                    ai.z += ei * r23.x + er * i23.x;
                    ai.w += ei * r23.y + er * i23.y;
                }
            }
        }
    }

    if (node < n) {
        float dn = __ldg(&d[node]);
        ar.x *= dn; ar.y *= dn; ar.z *= dn; ar.w *= dn;
        ai.x *= dn; ai.y *= dn; ai.z *= dn; ai.w *= dn;
        reinterpret_cast<float4*>(g_zr + (size_t)node * DIM)[l16] = ar;
        reinterpret_cast<float4*>(g_zi + (size_t)node * DIM)[l16] = ai;
    }
}

// ---------------------------------------------------------------------------
// K5: node dense layers with packed f32x2 FMA (FFMA2).
//   Lane handles output cols (j, j+32) as one 64-bit pair.
//   W staged pair-interleaved; z staged duplicated (zk,zk).
//   zr = (z_r@W1^T+b1) - (z_i@W2^T+b2)
//   zi = (zr @W2^T+b2) + (z_i@W1^T+b1)   (uses NEW zr)
// ---------------------------------------------------------------------------
#define NW  8
#define RPW 8

__global__ __launch_bounds__(NW * 32)
void node_kernel(const float* __restrict__ W1, const float* __restrict__ b1,
                 const float* __restrict__ W2, const float* __restrict__ b2,
                 float* __restrict__ out_zr, float* __restrict__ out_zi,
                 int n) {
    extern __shared__ char smraw[];
    // Wq[k2*32+c] : ulonglong2 =
    //   { (W[c][2k2],W[c+32][2k2]), (W[c][2k2+1],W[c+32][2k2+1]) }
    ulonglong2* Wq1 = reinterpret_cast<ulonglong2*>(smraw);
    ulonglong2* Wq2 = Wq1 + 32 * 32;
    float* b1s = reinterpret_cast<float*>(Wq2 + 32 * 32);
    float* b2s = b1s + DIM;
    unsigned long long* zbase =
        reinterpret_cast<unsigned long long*>(b2s + DIM);

    int tid = threadIdx.x, lane = tid & 31, w = tid >> 5;

    // FIX R6: bound is 32*32 pair-columns (k2 in [0,32) covers k in [0,64)
    // two at a time).  R5 iterated 64*32 and smashed Wq2/biases/z buffers.
    for (int idx = tid; idx < 32 * 32; idx += NW * 32) {
        int k2 = idx >> 5, c = idx & 31;
        int k0 = 2 * k2, k1 = 2 * k2 + 1;
        ulonglong2 v1, v2;
        v1.x = pk2(W1[c * 64 + k0], W1[(c + 32) * 64 + k0]);
        v1.y = pk2(W1[c * 64 + k1], W1[(c + 32) * 64 + k1]);
        v2.x = pk2(W2[c * 64 + k0], W2[(c + 32) * 64 + k0]);
        v2.y = pk2(W2[c * 64 + k1], W2[(c + 32) * 64 + k1]);
        Wq1[idx] = v1;
        Wq2[idx] = v2;
    }
    if (tid < DIM) { b1s[tid] = b1[tid]; b2s[tid] = b2[tid]; }
    __syncthreads();

    unsigned long long* zdr = zbase + (size_t)w * 3 * RPW * DIM;
    unsigned long long* zdi = zdr + RPW * DIM;
    unsigned long long* zdb = zdi + RPW * DIM;

    float bj1 = b1s[lane], bj1b = b1s[lane + 32];
    float bj2 = b2s[lane], bj2b = b2s[lane + 32];

    int nChunk = (n + RPW - 1) / RPW;
    for (int ch = blockIdx.x * NW + w; ch < nChunk; ch += gridDim.x * NW) {
        int rbase = ch * RPW;
        // ---- stage z rows duplicated ----
        #pragma unroll
        for (int r = 0; r < RPW; r++) {
            int row = rbase + r;
            if (row < n) {
                float2 a = reinterpret_cast<const float2*>(
                               g_zr + (size_t)row * DIM)[lane];
                float2 bq = reinterpret_cast<const float2*>(
                               g_zi + (size_t)row * DIM)[lane];
                zdr[r * DIM + 2 * lane]     = pk2(a.x, a.x);
                zdr[r * DIM + 2 * lane + 1] = pk2(a.y, a.y);
                zdi[r * DIM + 2 * lane]     = pk2(bq.x, bq.x);
                zdi[r * DIM + 2 * lane + 1] = pk2(bq.y, bq.y);
            }
        }
        __syncwarp();

        // ---- pass 1: zr ----
        unsigned long long accA[RPW], accB[RPW];
        #pragma unroll
        for (int r = 0; r < RPW; r++) { accA[r] = 0ull; accB[r] = 0ull; }
        #pragma unroll 4
        for (int k2 = 0; k2 < 32; k2++) {
            ulonglong2 w1 = Wq1[k2 * 32 + lane];
            ulonglong2 w2 = Wq2[k2 * 32 + lane];
            #pragma unroll
            for (int r = 0; r < RPW; r++) {
                ulonglong2 zr2 = reinterpret_cast<ulonglong2*>(zdr + r * DIM)[k2];
                ulonglong2 zi2 = reinterpret_cast<ulonglong2*>(zdi + r * DIM)[k2];
                accA[r] = fma2(zr2.x, w1.x, accA[r]);
                accA[r] = fma2(zr2.y, w1.y, accA[r]);
                accB[r] = fma2(zi2.x, w2.x, accB[r]);
                accB[r] = fma2(zi2.y, w2.y, accB[r]);
            }
        }
        #pragma unroll
        for (int r = 0; r < RPW; r++) {
            int row = rbase + r;
            float a0, a1, c0, c1;
            unpk2(accA[r], a0, a1);
            unpk2(accB[r], c0, c1);
            float zr0 = (a0 + bj1)  - (c0 + bj2);
            float zr1 = (a1 + bj1b) - (c1 + bj2b);
            zdb[r * DIM + lane]      = pk2(zr0, zr0);
            zdb[r * DIM + lane + 32] = pk2(zr1, zr1);
            if (row < n) {
                out_zr[(size_t)row * DIM + lane]      = zr0;
                out_zr[(size_t)row * DIM + lane + 32] = zr1;
            }
        }
        __syncwarp();

        // ---- pass 2: zi (uses NEW zr) ----
        #pragma unroll
        for (int r = 0; r < RPW; r++) { accA[r] = 0ull; accB[r] = 0ull; }
        #pragma unroll 4
        for (int k2 = 0; k2 < 32; k2++) {
            ulonglong2 w1 = Wq1[k2 * 32 + lane];
            ulonglong2 w2 = Wq2[k2 * 32 + lane];
            #pragma unroll
            for (int r = 0; r < RPW; r++) {
                ulonglong2 zb2 = reinterpret_cast<ulonglong2*>(zdb + r * DIM)[k2];
                ulonglong2 zi2 = reinterpret_cast<ulonglong2*>(zdi + r * DIM)[k2];
                accA[r] = fma2(zb2.x, w2.x, accA[r]);
                accA[r] = fma2(zb2.y, w2.y, accA[r]);
                accB[r] = fma2(zi2.x, w1.x, accB[r]);
                accB[r] = fma2(zi2.y, w1.y, accB[r]);
            }
        }
        #pragma unroll
        for (int r = 0; r < RPW; r++) {
            int row = rbase + r;
            if (row < n) {
                float a0, a1, c0, c1;
                unpk2(accA[r], a0, a1);
                unpk2(accB[r], c0, c1);
                out_zi[(size_t)row * DIM + lane]      = (a0 + bj2)  + (c0 + bj1);
                out_zi[(size_t)row * DIM + lane + 32] = (a1 + bj2b) + (c1 + bj1b);
            }
        }
        __syncwarp();
    }
}

// ---------------------------------------------------------------------------
extern "C" void kernel_launch(void* const* d_in, const int* in_sizes, int n_in,
                              void* d_out, int out_size) {
    const float* h_real = (const float*)d_in[0];
    const float* h_imag = (const float*)d_in[1];
    const float* d      = (const float*)d_in[2];
    const float* w_real = (const float*)d_in[3];
    const float* w_imag = (const float*)d_in[4];
    const int*   src    = (const int*)  d_in[5];
    const int*   dst    = (const int*)  d_in[6];
    const float* W1     = (const float*)d_in[7];
    const float* b1     = (const float*)d_in[8];
    const float* W2     = (const float*)d_in[9];
    const float* b2     = (const float*)d_in[10];

    int n = in_sizes[2];   // N_NODES
    int E = in_sizes[3];   // N_EDGES

    float* out_zr = (float*)d_out;
    float* out_zi = (float*)d_out + (size_t)n * DIM;

    init_kernel<<<(n * 16 + 255) / 256, 256>>>(h_real, h_imag, n);
    hist_kernel<<<(E + 1023) / 1024, 1024>>>(dst, E);
    offsets_kernel<<<(n + 255) / 256, 256>>>(n);
    permute_kernel<<<(E + 255) / 256, 256>>>(d, w_real, w_imag, src, dst, E);
    edge_kernel<<<(n + 15) / 16, 256>>>(d, n);

    size_t node_smem = 2 * 32 * 32 * sizeof(ulonglong2)        // Wq1, Wq2
                     + 2 * DIM * sizeof(float)                  // biases
                     + (size_t)NW * 3 * RPW * DIM * 8;          // z dup buffers
    cudaFuncSetAttribute(node_kernel,
                         cudaFuncAttributeMaxDynamicSharedMemorySize,
                         (int)node_smem);
    node_kernel<<<148, NW * 32, node_smem>>>(W1, b1, W2, b2,
                                             out_zr, out_zi, n);
}

// round 7
// speedup vs baseline: 1.1905x; 1.1905x over previous
#include <cuda_runtime.h>
#include <cuda_fp16.h>
#include <cstdint>

#define NMAX 100000
#define EMAX 1600000
#define DIM 64
#define PACKMAX (EMAX + 3 * NMAX + 64)

// ---- scratch (__device__ globals; alloc-free rule) -------------------------
__device__ int    g_cnt[NMAX];          // per-node degree
__device__ int    g_off[NMAX];          // bin offsets (padded)
__device__ int    g_cur[NMAX];          // write cursors
__device__ int    g_cursor;             // global bin allocator
__device__ float4 g_pack[PACKMAX];      // binned records: (src, er, ei, 0)
__device__ uint4  g_h[NMAX * 16];       // fp16 interleaved h per (node,l16)
__device__ float  g_z[NMAX * 128];      // [node][0:64)=z_real, [64:128)=z_imag
__device__ float  g_Wc[128 * 128];      // combined weight matrix
__device__ float  g_bc[128];            // combined bias

static __device__ __forceinline__ int round4(int x) { return (x + 3) & ~3; }

static __device__ __forceinline__ void unpk2(unsigned long long v,
                                             float& a, float& b) {
    asm("mov.b64 {%0, %1}, %2;" : "=f"(a), "=f"(b) : "l"(v));
}
static __device__ __forceinline__ unsigned long long fma2(
        unsigned long long a, unsigned long long b, unsigned long long c) {
    unsigned long long d;
    asm("fma.rn.f32x2 %0, %1, %2, %3;" : "=l"(d) : "l"(a), "l"(b), "l"(c));
    return d;
}

// ---------------------------------------------------------------------------
// K0: zero cnt + cursor, convert h to interleaved fp16
// ---------------------------------------------------------------------------
__global__ void init_kernel(const float* __restrict__ hr,
                            const float* __restrict__ hi, int n) {
    int t = blockIdx.x * blockDim.x + threadIdx.x;
    if (t == 0) g_cursor = 0;
    if (t < n) g_cnt[t] = 0;
    if (t < n * 16) {
        float4 r = __ldg(reinterpret_cast<const float4*>(hr) + t);
        float4 i = __ldg(reinterpret_cast<const float4*>(hi) + t);
        __half2 a = __floats2half2_rn(r.x, r.y);
        __half2 b = __floats2half2_rn(r.z, r.w);
        __half2 c = __floats2half2_rn(i.x, i.y);
        __half2 d = __floats2half2_rn(i.z, i.w);
        uint4 o;
        o.x = *reinterpret_cast<unsigned*>(&a);
        o.y = *reinterpret_cast<unsigned*>(&b);
        o.z = *reinterpret_cast<unsigned*>(&c);
        o.w = *reinterpret_cast<unsigned*>(&d);
        g_h[t] = o;
    }
}

// ---------------------------------------------------------------------------
// K1: histogram of dst
// ---------------------------------------------------------------------------
__global__ void hist_kernel(const int* __restrict__ dst, int E) {
    int e = blockIdx.x * blockDim.x + threadIdx.x;
    if (e < E) atomicAdd(&g_cnt[dst[e]], 1);
}

// ---------------------------------------------------------------------------
// K2: assign bin offsets (order-free warp scan + atomic), zero-fill padding
// ---------------------------------------------------------------------------
__global__ void offsets_kernel(int n) {
    int i = blockIdx.x * blockDim.x + threadIdx.x;
    int lane = threadIdx.x & 31;
    int deg = (i < n) ? g_cnt[i] : 0;
    int v = round4(deg);
    int x = v;
    #pragma unroll
    for (int o = 1; o < 32; o <<= 1) {
        int y = __shfl_up_sync(0xffffffffu, x, o);
        if (lane >= o) x += y;
    }
    int base = 0;
    if (lane == 31) base = atomicAdd(&g_cursor, x);
    base = __shfl_sync(0xffffffffu, base, 31);
    int off = base + x - v;
    if (i < n) {
        g_off[i] = off;
        g_cur[i] = off;
        for (int t = deg; t < v; t++)
            g_pack[off + t] = make_float4(0.f, 0.f, 0.f, 0.f);
    }
}

// ---------------------------------------------------------------------------
// K3: scatter packed records into dst bins (coefficient excludes d[dst])
// ---------------------------------------------------------------------------
__global__ void permute_kernel(const float* __restrict__ d,
                               const float* __restrict__ wr,
                               const float* __restrict__ wi,
                               const int*   __restrict__ src,
                               const int*   __restrict__ dst,
                               int E) {
    int e = blockIdx.x * blockDim.x + threadIdx.x;
    if (e >= E) return;
    int s  = src[e];
    int dd = dst[e];
    float ds = __ldg(&d[s]);
    int slot = atomicAdd(&g_cur[dd], 1);
    g_pack[slot] = make_float4(__int_as_float(s), ds * wr[e], ds * wi[e], 0.f);
}

// ---------------------------------------------------------------------------
// K3b: combine weights.
//   zr = Zr@W1^T - Zi@W2^T + (b1-b2)
//   zi = Zr@(W2@W1)^T + Zi@(W1 - W2@W2)^T + ((b1-b2)@W2^T + b1 + b2)
// Wc[j][k], j,k in [0,128): quadrants [W1 | -W2 ; M3 | M4]
// ---------------------------------------------------------------------------
__global__ void combine_kernel(const float* __restrict__ W1,
                               const float* __restrict__ b1,
                               const float* __restrict__ W2,
                               const float* __restrict__ b2) {
    __shared__ float W1s[64 * 64], W2s[64 * 64];
    int tid = threadIdx.x;
    for (int i = tid; i < 4096; i += 256) { W1s[i] = W1[i]; W2s[i] = W2[i]; }
    __syncthreads();
    int e = blockIdx.x * 256 + tid;          // 0..4095
    int j = e >> 6, k = e & 63;
    float m3 = 0.f, m4 = 0.f;
    #pragma unroll 4
    for (int t = 0; t < 64; t++) {
        float w2jt = W2s[j * 64 + t];
        m3 += w2jt * W1s[t * 64 + k];
        m4 += w2jt * W2s[t * 64 + k];
    }
    m4 = W1s[j * 64 + k] - m4;
    g_Wc[j * 128 + k]              = W1s[j * 64 + k];
    g_Wc[j * 128 + 64 + k]         = -W2s[j * 64 + k];
    g_Wc[(64 + j) * 128 + k]       = m3;
    g_Wc[(64 + j) * 128 + 64 + k]  = m4;
    if (j == 0) g_bc[k] = b1[k] - b2[k];
    if (k == 0) {
        float s = 0.f;
        for (int t = 0; t < 64; t++) s += (b1[t] - b2[t]) * W2s[j * 64 + t];
        g_bc[64 + j] = s + b1[j] + b2[j];
    }
}

// ---------------------------------------------------------------------------
// K4: edge gather-reduce (16 threads/node, coalesced record prefetch,
//     shuffle broadcast, one 16B fp16 gather per edge per lane).
// Writes Z unified: [node][0:64)=real, [64:128)=imag.
// ---------------------------------------------------------------------------
__global__ __launch_bounds__(256)
void edge_kernel(const float* __restrict__ d, int n) {
    int node = blockIdx.x * 16 + (threadIdx.x >> 4);
    int l16  = threadIdx.x & 15;
    unsigned hmask = (threadIdx.x & 16) ? 0xFFFF0000u : 0x0000FFFFu;

    int deg4 = 0, start = 0;
    if (node < n) {
        start = g_off[node];
        deg4  = round4(g_cnt[node]);
    }
    const float4* packp = g_pack + start;

    float4 ar = make_float4(0.f, 0.f, 0.f, 0.f);
    float4 ai = make_float4(0.f, 0.f, 0.f, 0.f);

    for (int base = 0; base < deg4; base += 16) {
        int m = min(16, deg4 - base);   // multiple of 4
        float4 p = make_float4(0.f, 0.f, 0.f, 0.f);
        if (l16 < m) p = __ldg(&packp[base + l16]);
        int ps = __float_as_int(p.x);

        #pragma unroll
        for (int c = 0; c < 4; c++) {
            if (c * 4 < m) {
                #pragma unroll
                for (int qq = 0; qq < 4; qq++) {
                    int q = c * 4 + qq;
                    int   s  = __shfl_sync(hmask, ps,  q, 16);
                    float er = __shfl_sync(hmask, p.y, q, 16);
                    float ei = __shfl_sync(hmask, p.z, q, 16);
                    uint4 hv = __ldg(&g_h[(s << 4) + l16]);
                    float2 r01 = __half22float2(*reinterpret_cast<__half2*>(&hv.x));
                    float2 r23 = __half22float2(*reinterpret_cast<__half2*>(&hv.y));
                    float2 i01 = __half22float2(*reinterpret_cast<__half2*>(&hv.z));
                    float2 i23 = __half22float2(*reinterpret_cast<__half2*>(&hv.w));
                    ar.x += er * r01.x - ei * i01.x;
                    ar.y += er * r01.y - ei * i01.y;
                    ar.z += er * r23.x - ei * i23.x;
                    ar.w += er * r23.y - ei * i23.y;
                    ai.x += ei * r01.x + er * i01.x;
                    ai.y += ei * r01.y + er * i01.y;
                    ai.z += ei * r23.x + er * i23.x;
                    ai.w += ei * r23.y + er * i23.y;
                }
            }
        }
    }

    if (node < n) {
        float dn = __ldg(&d[node]);
        ar.x *= dn; ar.y *= dn; ar.z *= dn; ar.w *= dn;
        ai.x *= dn; ai.y *= dn; ai.z *= dn; ai.w *= dn;
        reinterpret_cast<float4*>(g_z + (size_t)node * 128)[l16]     = ar;
        reinterpret_cast<float4*>(g_z + (size_t)node * 128 + 64)[l16] = ai;
    }
}

// ---------------------------------------------------------------------------
// K5: single-pass node GEMM  out = Z @ Wc^T + bc  with k-pair FFMA2.
//   Lane owns 4 output cols {lane, lane+32, 64+lane, 96+lane}; accumulators
//   are f32x2 partial (lo,hi) sums over k-pairs; no duplication MOVs.
//   W smem stride 132 floats -> conflict-free lane-distinct LDS.128.
// ---------------------------------------------------------------------------
#define NW  8
#define RPW 8
#define WSTRIDE 132

__global__ __launch_bounds__(NW * 32, 2)
void node_kernel(float* __restrict__ out_zr, float* __restrict__ out_zi,
                 int n) {
    extern __shared__ float sm[];
    float* Ws  = sm;                      // [128][WSTRIDE]
    float* bcs = Ws + 128 * WSTRIDE;      // [128]
    float* zst = bcs + 128;               // [NW][RPW][128]

    int tid = threadIdx.x, lane = tid & 31, w = tid >> 5;

    for (int i = tid; i < 128 * 32; i += NW * 32) {
        int row = i >> 5, kq = i & 31;
        reinterpret_cast<float4*>(Ws + row * WSTRIDE)[kq] =
            reinterpret_cast<const float4*>(g_Wc + row * 128)[kq];
    }
    if (tid < 128) bcs[tid] = g_bc[tid];
    __syncthreads();

    float* zw = zst + w * RPW * 128;
    const ulonglong2* w0 = reinterpret_cast<const ulonglong2*>(Ws + (lane)      * WSTRIDE);
    const ulonglong2* w1 = reinterpret_cast<const ulonglong2*>(Ws + (lane + 32) * WSTRIDE);
    const ulonglong2* w2 = reinterpret_cast<const ulonglong2*>(Ws + (64 + lane) * WSTRIDE);
    const ulonglong2* w3 = reinterpret_cast<const ulonglong2*>(Ws + (96 + lane) * WSTRIDE);

    float bj0 = bcs[lane], bj1 = bcs[lane + 32];
    float bj2 = bcs[64 + lane], bj3 = bcs[96 + lane];

    int nChunk = (n + RPW - 1) / RPW;
    for (int ch = blockIdx.x * NW + w; ch < nChunk; ch += gridDim.x * NW) {
        int rbase = ch * RPW;
        #pragma unroll
        for (int r = 0; r < RPW; r++) {
            int row = rbase + r;
            if (row < n)
                reinterpret_cast<float4*>(zw + r * 128)[lane] =
                    reinterpret_cast<const float4*>(g_z + (size_t)row * 128)[lane];
        }
        __syncwarp();

        unsigned long long acc0[RPW], acc1[RPW], acc2[RPW], acc3[RPW];
        #pragma unroll
        for (int r = 0; r < RPW; r++) {
            acc0[r] = 0ull; acc1[r] = 0ull; acc2[r] = 0ull; acc3[r] = 0ull;
        }
        #pragma unroll 2
        for (int k4 = 0; k4 < 32; k4++) {
            ulonglong2 a = w0[k4];
            ulonglong2 b = w1[k4];
            ulonglong2 c = w2[k4];
            ulonglong2 d = w3[k4];
            #pragma unroll
            for (int r = 0; r < RPW; r++) {
                ulonglong2 z = reinterpret_cast<const ulonglong2*>(zw + r * 128)[k4];
                acc0[r] = fma2(z.x, a.x, acc0[r]);
                acc0[r] = fma2(z.y, a.y, acc0[r]);
                acc1[r] = fma2(z.x, b.x, acc1[r]);
                acc1[r] = fma2(z.y, b.y, acc1[r]);
                acc2[r] = fma2(z.x, c.x, acc2[r]);
                acc2[r] = fma2(z.y, c.y, acc2[r]);
                acc3[r] = fma2(z.x, d.x, acc3[r]);
                acc3[r] = fma2(z.y, d.y, acc3[r]);
            }
        }
        #pragma unroll
        for (int r = 0; r < RPW; r++) {
            int row = rbase + r;
            if (row < n) {
                float lo, hi;
                unpk2(acc0[r], lo, hi);
                out_zr[(size_t)row * 64 + lane]      = lo + hi + bj0;
                unpk2(acc1[r], lo, hi);
                out_zr[(size_t)row * 64 + lane + 32] = lo + hi + bj1;
                unpk2(acc2[r], lo, hi);
                out_zi[(size_t)row * 64 + lane]      = lo + hi + bj2;
                unpk2(acc3[r], lo, hi);
                out_zi[(size_t)row * 64 + lane + 32] = lo + hi + bj3;
            }
        }
        __syncwarp();
    }
}

// ---------------------------------------------------------------------------
extern "C" void kernel_launch(void* const* d_in, const int* in_sizes, int n_in,
                              void* d_out, int out_size) {
    const float* h_real = (const float*)d_in[0];
    const float* h_imag = (const float*)d_in[1];
    const float* d      = (const float*)d_in[2];
    const float* w_real = (const float*)d_in[3];
    const float* w_imag = (const float*)d_in[4];
    const int*   src    = (const int*)  d_in[5];
    const int*   dst    = (const int*)  d_in[6];
    const float* W1     = (const float*)d_in[7];
    const float* b1     = (const float*)d_in[8];
    const float* W2     = (const float*)d_in[9];
    const float* b2     = (const float*)d_in[10];

    int n = in_sizes[2];   // N_NODES
    int E = in_sizes[3];   // N_EDGES

    float* out_zr = (float*)d_out;
    float* out_zi = (float*)d_out + (size_t)n * DIM;

    init_kernel<<<(n * 16 + 255) / 256, 256>>>(h_real, h_imag, n);
    hist_kernel<<<(E + 1023) / 1024, 1024>>>(dst, E);
    combine_kernel<<<16, 256>>>(W1, b1, W2, b2);
    offsets_kernel<<<(n + 255) / 256, 256>>>(n);
    permute_kernel<<<(E + 255) / 256, 256>>>(d, w_real, w_imag, src, dst, E);
    edge_kernel<<<(n + 15) / 16, 256>>>(d, n);

    size_t node_smem = (size_t)(128 * WSTRIDE + 128 + NW * RPW * 128)
                       * sizeof(float);
    cudaFuncSetAttribute(node_kernel,
                         cudaFuncAttributeMaxDynamicSharedMemorySize,
                         (int)node_smem);
    node_kernel<<<296, NW * 32, node_smem>>>(out_zr, out_zi, n);
}

// round 8
// speedup vs baseline: 1.2861x; 1.0803x over previous
#include <cuda_runtime.h>
#include <cuda_fp16.h>
#include <cstdint>

#define NMAX 100000
#define EMAX 1600000
#define DIM 64
#define PACKMAX (EMAX + 3 * NMAX + 64)

// ---- scratch (__device__ globals; alloc-free rule) -------------------------
// g_cnt / g_cursor are zero-initialized at module load and RESTORED to zero by
// edge_kernel at the end of every call, so each graph replay sees them zeroed.
__device__ int    g_cnt[NMAX];          // per-node degree
__device__ int    g_off[NMAX];          // bin offsets (padded)
__device__ int    g_cur[NMAX];          // write cursors
__device__ int    g_cursor;             // global bin allocator
__device__ uint2  g_pack[PACKMAX];      // binned records: (src, half2(er,ei))
__device__ uint4  g_h[NMAX * 16];       // fp16 interleaved h per (node,l16)
__device__ float  g_z[NMAX * 128];      // [node][0:64)=z_real, [64:128)=z_imag
__device__ float  g_Wc[128 * 128];      // combined weight matrix
__device__ float  g_bc[128];            // combined bias

static __device__ __forceinline__ int round4(int x) { return (x + 3) & ~3; }

static __device__ __forceinline__ void unpk2(unsigned long long v,
                                             float& a, float& b) {
    asm("mov.b64 {%0, %1}, %2;" : "=f"(a), "=f"(b) : "l"(v));
}
static __device__ __forceinline__ unsigned long long fma2(
        unsigned long long a, unsigned long long b, unsigned long long c) {
    unsigned long long d;
    asm("fma.rn.f32x2 %0, %1, %2, %3;" : "=l"(d) : "l"(a), "l"(b), "l"(c));
    return d;
}

// ---------------------------------------------------------------------------
// K1: fused dst-histogram + h->fp16 interleave (same grid covers both)
// ---------------------------------------------------------------------------
__global__ void histcvt_kernel(const int* __restrict__ dst,
                               const float* __restrict__ hr,
                               const float* __restrict__ hi,
                               int E, int n) {
    int t = blockIdx.x * blockDim.x + threadIdx.x;
    if (t < E) atomicAdd(&g_cnt[dst[t]], 1);
    if (t < n * 16) {
        float4 r = __ldg(reinterpret_cast<const float4*>(hr) + t);
        float4 i = __ldg(reinterpret_cast<const float4*>(hi) + t);
        __half2 a = __floats2half2_rn(r.x, r.y);
        __half2 b = __floats2half2_rn(r.z, r.w);
        __half2 c = __floats2half2_rn(i.x, i.y);
        __half2 d = __floats2half2_rn(i.z, i.w);
        uint4 o;
        o.x = *reinterpret_cast<unsigned*>(&a);
        o.y = *reinterpret_cast<unsigned*>(&b);
        o.z = *reinterpret_cast<unsigned*>(&c);
        o.w = *reinterpret_cast<unsigned*>(&d);
        g_h[t] = o;
    }
}

// ---------------------------------------------------------------------------
// K2: assign bin offsets (order-free warp scan + atomic), zero-fill padding
// ---------------------------------------------------------------------------
__global__ void offsets_kernel(int n) {
    int i = blockIdx.x * blockDim.x + threadIdx.x;
    int lane = threadIdx.x & 31;
    int deg = (i < n) ? g_cnt[i] : 0;
    int v = round4(deg);
    int x = v;
    #pragma unroll
    for (int o = 1; o < 32; o <<= 1) {
        int y = __shfl_up_sync(0xffffffffu, x, o);
        if (lane >= o) x += y;
    }
    int base = 0;
    if (lane == 31) base = atomicAdd(&g_cursor, x);
    base = __shfl_sync(0xffffffffu, base, 31);
    int off = base + x - v;
    if (i < n) {
        g_off[i] = off;
        g_cur[i] = off;
        for (int t = deg; t < v; t++)
            g_pack[off + t] = make_uint2(0u, 0u);
    }
}

// ---------------------------------------------------------------------------
// K3: scatter 8-byte records into dst bins (coefficient excludes d[dst])
// ---------------------------------------------------------------------------
__global__ void permute_kernel(const float* __restrict__ d,
                               const float* __restrict__ wr,
                               const float* __restrict__ wi,
                               const int*   __restrict__ src,
                               const int*   __restrict__ dst,
                               int E) {
    int e = blockIdx.x * blockDim.x + threadIdx.x;
    if (e >= E) return;
    int s  = src[e];
    int dd = dst[e];
    float ds = __ldg(&d[s]);
    __half2 eh = __floats2half2_rn(ds * wr[e], ds * wi[e]);
    int slot = atomicAdd(&g_cur[dd], 1);
    g_pack[slot] = make_uint2((unsigned)s, *reinterpret_cast<unsigned*>(&eh));
}

// ---------------------------------------------------------------------------
// K4: edge gather-reduce (16 threads/node, coalesced 8B record prefetch,
//     shuffle broadcast, one 16B fp16 gather per edge per lane).
// Restores g_cnt / g_cursor to zero for the next graph replay.
// ---------------------------------------------------------------------------
__global__ __launch_bounds__(256)
void edge_kernel(const float* __restrict__ d, int n) {
    int node = blockIdx.x * 16 + (threadIdx.x >> 4);
    int l16  = threadIdx.x & 15;
    unsigned hmask = (threadIdx.x & 16) ? 0xFFFF0000u : 0x0000FFFFu;

    int deg4 = 0, start = 0;
    if (node < n) {
        start = g_off[node];
        deg4  = round4(g_cnt[node]);
    }
    const uint2* packp = g_pack + start;

    float4 ar = make_float4(0.f, 0.f, 0.f, 0.f);
    float4 ai = make_float4(0.f, 0.f, 0.f, 0.f);

    for (int base = 0; base < deg4; base += 16) {
        int m = min(16, deg4 - base);   // multiple of 4
        uint2 p = make_uint2(0u, 0u);
        if (l16 < m) p = __ldg(&packp[base + l16]);

        #pragma unroll
        for (int c = 0; c < 4; c++) {
            if (c * 4 < m) {
                #pragma unroll
                for (int qq = 0; qq < 4; qq++) {
                    int q = c * 4 + qq;
                    unsigned s  = __shfl_sync(hmask, p.x, q, 16);
                    unsigned e2 = __shfl_sync(hmask, p.y, q, 16);
                    float2 ef = __half22float2(
                        *reinterpret_cast<__half2*>(&e2));
                    float er = ef.x, ei = ef.y;
                    uint4 hv = __ldg(&g_h[(s << 4) + l16]);
                    float2 r01 = __half22float2(*reinterpret_cast<__half2*>(&hv.x));
                    float2 r23 = __half22float2(*reinterpret_cast<__half2*>(&hv.y));
                    float2 i01 = __half22float2(*reinterpret_cast<__half2*>(&hv.z));
                    float2 i23 = __half22float2(*reinterpret_cast<__half2*>(&hv.w));
                    ar.x += er * r01.x - ei * i01.x;
                    ar.y += er * r01.y - ei * i01.y;
                    ar.z += er * r23.x - ei * i23.x;
                    ar.w += er * r23.y - ei * i23.y;
                    ai.x += ei * r01.x + er * i01.x;
                    ai.y += ei * r01.y + er * i01.y;
                    ai.z += ei * r23.x + er * i23.x;
                    ai.w += ei * r23.y + er * i23.y;
                }
            }
        }
    }

    if (node < n) {
        float dn = __ldg(&d[node]);
        ar.x *= dn; ar.y *= dn; ar.z *= dn; ar.w *= dn;
        ai.x *= dn; ai.y *= dn; ai.z *= dn; ai.w *= dn;
        reinterpret_cast<float4*>(g_z + (size_t)node * 128)[l16]      = ar;
        reinterpret_cast<float4*>(g_z + (size_t)node * 128 + 64)[l16] = ai;
    }

    // ---- restore per-call state for the next graph replay ----
    __syncwarp();
    if (l16 == 0 && node < n) g_cnt[node] = 0;
    if (blockIdx.x == 0 && threadIdx.x == 0) g_cursor = 0;
}

// ---------------------------------------------------------------------------
// K5: combine weights.
//   zr = Zr@W1^T - Zi@W2^T + (b1-b2)
//   zi = Zr@(W2@W1)^T + Zi@(W1 - W2@W2)^T + ((b1-b2)@W2^T + b1 + b2)
// Wc quadrants: [W1 | -W2 ; W2@W1 | W1-W2@W2]
// ---------------------------------------------------------------------------
__global__ void combine_kernel(const float* __restrict__ W1,
                               const float* __restrict__ b1,
                               const float* __restrict__ W2,
                               const float* __restrict__ b2) {
    __shared__ float W1s[64 * 64], W2s[64 * 64];
    int tid = threadIdx.x;
    for (int i = tid; i < 4096; i += 256) { W1s[i] = W1[i]; W2s[i] = W2[i]; }
    __syncthreads();
    int e = blockIdx.x * 256 + tid;          // 0..4095
    int j = e >> 6, k = e & 63;
    float m3 = 0.f, m4 = 0.f;
    #pragma unroll 4
    for (int t = 0; t < 64; t++) {
        float w2jt = W2s[j * 64 + t];
        m3 += w2jt * W1s[t * 64 + k];
        m4 += w2jt * W2s[t * 64 + k];
    }
    m4 = W1s[j * 64 + k] - m4;
    g_Wc[j * 128 + k]              = W1s[j * 64 + k];
    g_Wc[j * 128 + 64 + k]         = -W2s[j * 64 + k];
    g_Wc[(64 + j) * 128 + k]       = m3;
    g_Wc[(64 + j) * 128 + 64 + k]  = m4;
    if (j == 0) g_bc[k] = b1[k] - b2[k];
    if (k == 0) {
        float s = 0.f;
        for (int t = 0; t < 64; t++) s += (b1[t] - b2[t]) * W2s[j * 64 + t];
        g_bc[64 + j] = s + b1[j] + b2[j];
    }
}

// ---------------------------------------------------------------------------
// K6: single-pass node GEMM  out = Z @ Wc^T + bc  with k-pair FFMA2.
// ---------------------------------------------------------------------------
#define NW  8
#define RPW 8
#define WSTRIDE 132

__global__ __launch_bounds__(NW * 32, 2)
void node_kernel(float* __restrict__ out_zr, float* __restrict__ out_zi,
                 int n) {
    extern __shared__ float sm[];
    float* Ws  = sm;                      // [128][WSTRIDE]
    float* bcs = Ws + 128 * WSTRIDE;      // [128]
    float* zst = bcs + 128;               // [NW][RPW][128]

    int tid = threadIdx.x, lane = tid & 31, w = tid >> 5;

    for (int i = tid; i < 128 * 32; i += NW * 32) {
        int row = i >> 5, kq = i & 31;
        reinterpret_cast<float4*>(Ws + row * WSTRIDE)[kq] =
            reinterpret_cast<const float4*>(g_Wc + row * 128)[kq];
    }
    if (tid < 128) bcs[tid] = g_bc[tid];
    __syncthreads();

    float* zw = zst + w * RPW * 128;
    const ulonglong2* w0 = reinterpret_cast<const ulonglong2*>(Ws + (lane)      * WSTRIDE);
    const ulonglong2* w1 = reinterpret_cast<const ulonglong2*>(Ws + (lane + 32) * WSTRIDE);
    const ulonglong2* w2 = reinterpret_cast<const ulonglong2*>(Ws + (64 + lane) * WSTRIDE);
    const ulonglong2* w3 = reinterpret_cast<const ulonglong2*>(Ws + (96 + lane) * WSTRIDE);

    float bj0 = bcs[lane], bj1 = bcs[lane + 32];
    float bj2 = bcs[64 + lane], bj3 = bcs[96 + lane];

    int nChunk = (n + RPW - 1) / RPW;
    for (int ch = blockIdx.x * NW + w; ch < nChunk; ch += gridDim.x * NW) {
        int rbase = ch * RPW;
        #pragma unroll
        for (int r = 0; r < RPW; r++) {
            int row = rbase + r;
            if (row < n)
                reinterpret_cast<float4*>(zw + r * 128)[lane] =
                    reinterpret_cast<const float4*>(g_z + (size_t)row * 128)[lane];
        }
        __syncwarp();

        unsigned long long acc0[RPW], acc1[RPW], acc2[RPW], acc3[RPW];
        #pragma unroll
        for (int r = 0; r < RPW; r++) {
            acc0[r] = 0ull; acc1[r] = 0ull; acc2[r] = 0ull; acc3[r] = 0ull;
        }
        #pragma unroll 2
        for (int k4 = 0; k4 < 32; k4++) {
            ulonglong2 a = w0[k4];
            ulonglong2 b = w1[k4];
            ulonglong2 c = w2[k4];
            ulonglong2 d = w3[k4];
            #pragma unroll
            for (int r = 0; r < RPW; r++) {
                ulonglong2 z = reinterpret_cast<const ulonglong2*>(zw + r * 128)[k4];
                acc0[r] = fma2(z.x, a.x, acc0[r]);
                acc0[r] = fma2(z.y, a.y, acc0[r]);
                acc1[r] = fma2(z.x, b.x, acc1[r]);
                acc1[r] = fma2(z.y, b.y, acc1[r]);
                acc2[r] = fma2(z.x, c.x, acc2[r]);
                acc2[r] = fma2(z.y, c.y, acc2[r]);
                acc3[r] = fma2(z.x, d.x, acc3[r]);
                acc3[r] = fma2(z.y, d.y, acc3[r]);
            }
        }
        #pragma unroll
        for (int r = 0; r < RPW; r++) {
            int row = rbase + r;
            if (row < n) {
                float lo, hi;
                unpk2(acc0[r], lo, hi);
                out_zr[(size_t)row * 64 + lane]      = lo + hi + bj0;
                unpk2(acc1[r], lo, hi);
                out_zr[(size_t)row * 64 + lane + 32] = lo + hi + bj1;
                unpk2(acc2[r], lo, hi);
                out_zi[(size_t)row * 64 + lane]      = lo + hi + bj2;
                unpk2(acc3[r], lo, hi);
                out_zi[(size_t)row * 64 + lane + 32] = lo + hi + bj3;
            }
        }
        __syncwarp();
    }
}

// ---------------------------------------------------------------------------
extern "C" void kernel_launch(void* const* d_in, const int* in_sizes, int n_in,
                              void* d_out, int out_size) {
    const float* h_real = (const float*)d_in[0];
    const float* h_imag = (const float*)d_in[1];
    const float* d      = (const float*)d_in[2];
    const float* w_real = (const float*)d_in[3];
    const float* w_imag = (const float*)d_in[4];
    const int*   src    = (const int*)  d_in[5];
    const int*   dst    = (const int*)  d_in[6];
    const float* W1     = (const float*)d_in[7];
    const float* b1     = (const float*)d_in[8];
    const float* W2     = (const float*)d_in[9];
    const float* b2     = (const float*)d_in[10];

    int n = in_sizes[2];   // N_NODES
    int E = in_sizes[3];   // N_EDGES

    float* out_zr = (float*)d_out;
    float* out_zi = (float*)d_out + (size_t)n * DIM;

    int tmax = (E > n * 16) ? E : n * 16;

    // Launch order puts edge_kernel at position #4 (the profiled slot).
    histcvt_kernel<<<(tmax + 255) / 256, 256>>>(dst, h_real, h_imag, E, n);
    offsets_kernel<<<(n + 255) / 256, 256>>>(n);
    permute_kernel<<<(E + 255) / 256, 256>>>(d, w_real, w_imag, src, dst, E);
    edge_kernel<<<(n + 15) / 16, 256>>>(d, n);
    combine_kernel<<<16, 256>>>(W1, b1, W2, b2);

    size_t node_smem = (size_t)(128 * WSTRIDE + 128 + NW * RPW * 128)
                       * sizeof(float);
    cudaFuncSetAttribute(node_kernel,
                         cudaFuncAttributeMaxDynamicSharedMemorySize,
                         (int)node_smem);
    node_kernel<<<296, NW * 32, node_smem>>>(out_zr, out_zi, n);
}